// round 11
// baseline (speedup 1.0000x reference)
#include <cuda_runtime.h>
#include <cuda_bf16.h>
#include <float.h>

// Packed {scale (lo 32b), 1/scale (hi 32b)}. Zero means "not yet published".
// scale > 0 always, so the published value is never 0 — the value is its own
// ready flag. 64-bit accesses are single atomic LDG.64/STG.64.
__device__ volatile unsigned long long g_scale_packed;

// ---------------------------------------------------------------------------
// Grid 1025:
//   block 0       : compute scale = max|W|/7, publish packed {s, 1/s}.
//   blocks 1..1024: 8 warps each; every WARP independently processes ONE
//                   batch row (8192 warps = 8192 rows). Per row: MaxPool3d(2)
//                   + inline int4-dequant linear(2048->4), warp-shuffle
//                   reduction (no block barriers in the worker path),
//                   lane 0 softmax + one STG.128.
//
// vs R9 (best, 80.3us): same resident-warp count (~40/SM), but each warp is
// fully autonomous — one barrier-free epilogue per 64KB streamed instead of a
// block-wide __syncthreads epilogue per 32KB, and ~2 waves instead of ~7.
// vs R10 (failed, 100us): 4x the warps; restores the latency hiding that the
// single-wave config lacked.
//
// Per-row indexing (row base xr = x + row*16384 floats):
//   lane handles feature-pairs fp = lane + i*32, i = 0..31
//   off(fp) = i*512 + (lane>>2)*32 + (lane&3)*4   [floats]
//   4 loads per fp: off, off+16, off+256, off+272  (float4, sector-complete)
//   weights at fp*2 = i*64 + lane*2 (+ {0,2048,4096,6144} per output)
// ---------------------------------------------------------------------------
__global__ void __launch_bounds__(256)
fused_pool_linear_softmax_kernel(const float* __restrict__ x,
                                 const float* __restrict__ W,
                                 const float* __restrict__ bias,
                                 float* __restrict__ out) {
    const int t = threadIdx.x;

    // ---------------- block 0: scale producer ----------------
    if (blockIdx.x == 0) {
        __shared__ float s_warp[8];
        const float4* __restrict__ W4 = reinterpret_cast<const float4*>(W);
        float m = 0.0f;
        #pragma unroll
        for (int k = 0; k < 8; k++) {
            const float4 w = W4[t + k * 256];
            m = fmaxf(m, fmaxf(fmaxf(fabsf(w.x), fabsf(w.y)),
                               fmaxf(fabsf(w.z), fabsf(w.w))));
        }
        #pragma unroll
        for (int off = 16; off > 0; off >>= 1)
            m = fmaxf(m, __shfl_xor_sync(0xFFFFFFFFu, m, off));
        if ((t & 31) == 0) s_warp[t >> 5] = m;
        __syncthreads();
        if (t == 0) {
            float mm = fmaxf(fmaxf(fmaxf(s_warp[0], s_warp[1]),
                                   fmaxf(s_warp[2], s_warp[3])),
                             fmaxf(fmaxf(s_warp[4], s_warp[5]),
                                   fmaxf(s_warp[6], s_warp[7])));
            const float scale = mm / 7.0f;
            const float inv_scale = 1.0f / scale;
            const unsigned long long packed =
                ((unsigned long long)__float_as_uint(inv_scale) << 32) |
                (unsigned long long)__float_as_uint(scale);
            g_scale_packed = packed;   // volatile 64-bit store: flag == data
        }
        return;
    }

    // ---------------- worker warps: one row each ----------------
    const int lane = t & 31;
    const int wid  = t >> 5;
    const int row  = (blockIdx.x - 1) * 8 + wid;     // 0..8191

    const float4 bias4 = *reinterpret_cast<const float4*>(bias);

    // Issue first loads before the scale spin (they don't depend on scale).
    const int laneoff = (lane >> 2) * 32 + (lane & 3) * 4;   // float offset
    const int wbase   = lane * 2;                            // weight float2 base
    const float* __restrict__ xr = x + (size_t)row * 16384 + laneoff;

    // Spin for the packed scale (single L2 load once published).
    unsigned long long v = g_scale_packed;
    while (v == 0ull) v = g_scale_packed;
    const float scale     = __uint_as_float((unsigned int)v);
    const float inv_scale = __uint_as_float((unsigned int)(v >> 32));

    float l0 = 0.0f, l1 = 0.0f, l2 = 0.0f, l3 = 0.0f;

    #pragma unroll 8
    for (int i = 0; i < 32; i++) {
        const float4* p = reinterpret_cast<const float4*>(xr + i * 512);
        const float4 a0 = __ldcs(p);        // (d0, h0)
        const float4 a1 = __ldcs(p + 4);    // (d0, h1)
        const float4 a2 = __ldcs(p + 64);   // (d1, h0)
        const float4 a3 = __ldcs(p + 68);   // (d1, h1)

        const float m0 = fmaxf(fmaxf(fmaxf(a0.x, a0.y), fmaxf(a1.x, a1.y)),
                               fmaxf(fmaxf(a2.x, a2.y), fmaxf(a3.x, a3.y)));
        const float m1 = fmaxf(fmaxf(fmaxf(a0.z, a0.w), fmaxf(a1.z, a1.w)),
                               fmaxf(fmaxf(a2.z, a2.w), fmaxf(a3.z, a3.w)));

        const int f2 = i * 64 + wbase;
        float2 w0 = *reinterpret_cast<const float2*>(&W[f2]);
        float2 w1 = *reinterpret_cast<const float2*>(&W[2048 + f2]);
        float2 w2 = *reinterpret_cast<const float2*>(&W[4096 + f2]);
        float2 w3 = *reinterpret_cast<const float2*>(&W[6144 + f2]);

        // inline int4 dequant (half-to-even; clip(-8,7) never binds)
        w0.x = rintf(w0.x * inv_scale) * scale;
        w0.y = rintf(w0.y * inv_scale) * scale;
        w1.x = rintf(w1.x * inv_scale) * scale;
        w1.y = rintf(w1.y * inv_scale) * scale;
        w2.x = rintf(w2.x * inv_scale) * scale;
        w2.y = rintf(w2.y * inv_scale) * scale;
        w3.x = rintf(w3.x * inv_scale) * scale;
        w3.y = rintf(w3.y * inv_scale) * scale;

        l0 = fmaf(m0, w0.x, fmaf(m1, w0.y, l0));
        l1 = fmaf(m0, w1.x, fmaf(m1, w1.y, l1));
        l2 = fmaf(m0, w2.x, fmaf(m1, w2.y, l2));
        l3 = fmaf(m0, w3.x, fmaf(m1, w3.y, l3));
    }

    // warp-only reduction (no barriers)
    #pragma unroll
    for (int off = 16; off > 0; off >>= 1) {
        l0 += __shfl_xor_sync(0xFFFFFFFFu, l0, off);
        l1 += __shfl_xor_sync(0xFFFFFFFFu, l1, off);
        l2 += __shfl_xor_sync(0xFFFFFFFFu, l2, off);
        l3 += __shfl_xor_sync(0xFFFFFFFFu, l3, off);
    }

    if (lane == 0) {
        l0 += bias4.x;  l1 += bias4.y;  l2 += bias4.z;  l3 += bias4.w;
        const float mx = fmaxf(fmaxf(l0, l1), fmaxf(l2, l3));
        const float e0 = __expf(l0 - mx);
        const float e1 = __expf(l1 - mx);
        const float e2 = __expf(l2 - mx);
        const float e3 = __expf(l3 - mx);
        const float inv = 1.0f / (e0 + e1 + e2 + e3);
        float4 r = make_float4(e0 * inv, e1 * inv, e2 * inv, e3 * inv);
        *reinterpret_cast<float4*>(out + (size_t)row * 4) = r;
    }
}

extern "C" void kernel_launch(void* const* d_in, const int* in_sizes, int n_in,
                              void* d_out, int out_size) {
    const float* x = (const float*)d_in[0];   // [8192,4,16,16,16]
    const float* W = (const float*)d_in[1];   // [4,2048]
    const float* b = (const float*)d_in[2];   // [4]
    float* out = (float*)d_out;               // [8192,4]

    fused_pool_linear_softmax_kernel<<<1025, 256>>>(x, W, b, out);
}

// round 12
// speedup vs baseline: 1.2665x; 1.2665x over previous
#include <cuda_runtime.h>
#include <cuda_bf16.h>
#include <float.h>

// Packed {scale (lo 32b), 1/scale (hi 32b)}. Zero means "not yet published".
// scale > 0 always, so the published value is never 0 — the value is its own
// ready flag. 64-bit accesses are single atomic LDG.64/STG.64.
__device__ volatile unsigned long long g_scale_packed;

// ---------------------------------------------------------------------------
// Single fused kernel, grid 4097 (R9 structure — best measured: 80.3us,
// 84.7% DRAM — plus weight-prefetch pipelining):
//   block 0     : compute scale = max|W|/7, publish packed {s, 1/s}.
//   blocks 1..N : MaxPool3d(2) + inline int4-dequant linear(2048->4) + bias
//                 + softmax, 2 batch rows per block, CTA-cooperative
//                 contiguous sweeps (one ~16KB region per row per k-iter).
// k=0 x loads + k=0 raw weight loads issue BEFORE the scale spin; raw weights
// for k+1 are prefetched during k's processing so the L1/L2 weight-load
// latency never sits on the FMA path.
//
// x layout: [B, C=4, D=16, H=16, W=16] f32, 16384 floats per row.
// pair index fp in [0,1024): c = fp>>8, rem = fp&255,
//   pd = rem>>5, ph = (rem>>2)&7, pwp = rem&3
// base float offset = c*4096 + pd*512 + ph*32 + pwp*4
// ---------------------------------------------------------------------------
__global__ void __launch_bounds__(256)
fused_pool_linear_softmax_kernel(const float* __restrict__ x,
                                 const float* __restrict__ W,
                                 const float* __restrict__ bias,
                                 float* __restrict__ out) {
    const int t = threadIdx.x;

    // ---------------- block 0: scale producer ----------------
    if (blockIdx.x == 0) {
        __shared__ float s_warp[8];
        const float4* __restrict__ W4 = reinterpret_cast<const float4*>(W);
        float m = 0.0f;
        #pragma unroll
        for (int k = 0; k < 8; k++) {
            const float4 w = W4[t + k * 256];
            m = fmaxf(m, fmaxf(fmaxf(fabsf(w.x), fabsf(w.y)),
                               fmaxf(fabsf(w.z), fabsf(w.w))));
        }
        #pragma unroll
        for (int off = 16; off > 0; off >>= 1)
            m = fmaxf(m, __shfl_xor_sync(0xFFFFFFFFu, m, off));
        if ((t & 31) == 0) s_warp[t >> 5] = m;
        __syncthreads();
        if (t == 0) {
            float mm = fmaxf(fmaxf(fmaxf(s_warp[0], s_warp[1]),
                                   fmaxf(s_warp[2], s_warp[3])),
                             fmaxf(fmaxf(s_warp[4], s_warp[5]),
                                   fmaxf(s_warp[6], s_warp[7])));
            const float scale = mm / 7.0f;
            const float inv_scale = 1.0f / scale;
            const unsigned long long packed =
                ((unsigned long long)__float_as_uint(inv_scale) << 32) |
                (unsigned long long)__float_as_uint(scale);
            g_scale_packed = packed;   // volatile 64-bit store: flag == data
        }
        return;
    }

    // ---------------- blocks 1..4096: main body ----------------
    __shared__ float s_red[8][8];   // [warp][row0 accs 0..3 | row1 accs 4..7]

    const int b0 = (blockIdx.x - 1) * 2;
    const float* __restrict__ xb0 = x + (size_t)b0 * 16384;
    const float* __restrict__ xb1 = xb0 + 16384;

    const float4 bias4 = *reinterpret_cast<const float4*>(bias);

    float p0 = 0.0f, p1 = 0.0f, p2 = 0.0f, p3 = 0.0f;   // row 0 partials
    float q0 = 0.0f, q1 = 0.0f, q2 = 0.0f, q3 = 0.0f;   // row 1 partials

    // per-k base offsets (k-invariant pieces precomputed)
    const int rem0 = t & 255;
    const int c_0  = t >> 8;   // 0 for 256 threads, kept for clarity
    const int loff = c_0 * 4096 + (rem0 >> 5) * 512 + ((rem0 >> 2) & 7) * 32
                     + (rem0 & 3) * 4;

    // ===== peeled k=0: issue x loads + raw weight loads BEFORE the spin =====
    const float4* pa0 = reinterpret_cast<const float4*>(xb0 + loff);
    const float4* pb0 = reinterpret_cast<const float4*>(xb1 + loff);
    float4 A0 = __ldcs(pa0);
    float4 A1 = __ldcs(pa0 + 4);
    float4 A2 = __ldcs(pa0 + 64);
    float4 A3 = __ldcs(pa0 + 68);
    float4 C0 = __ldcs(pb0);
    float4 C1 = __ldcs(pb0 + 4);
    float4 C2 = __ldcs(pb0 + 64);
    float4 C3 = __ldcs(pb0 + 68);

    // raw weights for k=0 (scale-independent)
    int f2 = t * 2;
    float2 rw0 = *reinterpret_cast<const float2*>(&W[f2]);
    float2 rw1 = *reinterpret_cast<const float2*>(&W[2048 + f2]);
    float2 rw2 = *reinterpret_cast<const float2*>(&W[4096 + f2]);
    float2 rw3 = *reinterpret_cast<const float2*>(&W[6144 + f2]);

    // Spin for the packed scale; everything above is in flight meanwhile.
    unsigned long long v = g_scale_packed;
    while (v == 0ull) v = g_scale_packed;
    const float scale     = __uint_as_float((unsigned int)v);
    const float inv_scale = __uint_as_float((unsigned int)(v >> 32));

    #pragma unroll
    for (int k = 0; k < 4; k++) {
        // current iteration's weights arrive via rw* (prefetched)
        float2 w0 = rw0, w1 = rw1, w2 = rw2, w3 = rw3;

        // prefetch raw weights for k+1 (L1 hit; overlaps with math below)
        if (k < 3) {
            const int nf2 = (t + (k + 1) * 256) * 2;
            rw0 = *reinterpret_cast<const float2*>(&W[nf2]);
            rw1 = *reinterpret_cast<const float2*>(&W[2048 + nf2]);
            rw2 = *reinterpret_cast<const float2*>(&W[4096 + nf2]);
            rw3 = *reinterpret_cast<const float2*>(&W[6144 + nf2]);
        }

        // pooled maxes for current k (loads already in flight)
        const float ma0 = fmaxf(fmaxf(fmaxf(A0.x, A0.y), fmaxf(A1.x, A1.y)),
                                fmaxf(fmaxf(A2.x, A2.y), fmaxf(A3.x, A3.y)));
        const float ma1 = fmaxf(fmaxf(fmaxf(A0.z, A0.w), fmaxf(A1.z, A1.w)),
                                fmaxf(fmaxf(A2.z, A2.w), fmaxf(A3.z, A3.w)));
        const float mb0 = fmaxf(fmaxf(fmaxf(C0.x, C0.y), fmaxf(C1.x, C1.y)),
                                fmaxf(fmaxf(C2.x, C2.y), fmaxf(C3.x, C3.y)));
        const float mb1 = fmaxf(fmaxf(fmaxf(C0.z, C0.w), fmaxf(C1.z, C1.w)),
                                fmaxf(fmaxf(C2.z, C2.w), fmaxf(C3.z, C3.w)));

        // issue x loads for k+1 right after current values are consumed
        if (k < 3) {
            const int fp  = t + (k + 1) * 256;
            const int c   = fp >> 8;
            const int rem = fp & 255;
            const int off = c * 4096 + (rem >> 5) * 512 + ((rem >> 2) & 7) * 32
                            + (rem & 3) * 4;
            const float4* pa = reinterpret_cast<const float4*>(xb0 + off);
            const float4* pb = reinterpret_cast<const float4*>(xb1 + off);
            A0 = __ldcs(pa);
            A1 = __ldcs(pa + 4);
            A2 = __ldcs(pa + 64);
            A3 = __ldcs(pa + 68);
            C0 = __ldcs(pb);
            C1 = __ldcs(pb + 4);
            C2 = __ldcs(pb + 64);
            C3 = __ldcs(pb + 68);
        }

        // inline int4 dequant (half-to-even; clip(-8,7) never binds)
        w0.x = rintf(w0.x * inv_scale) * scale;
        w0.y = rintf(w0.y * inv_scale) * scale;
        w1.x = rintf(w1.x * inv_scale) * scale;
        w1.y = rintf(w1.y * inv_scale) * scale;
        w2.x = rintf(w2.x * inv_scale) * scale;
        w2.y = rintf(w2.y * inv_scale) * scale;
        w3.x = rintf(w3.x * inv_scale) * scale;
        w3.y = rintf(w3.y * inv_scale) * scale;

        p0 = fmaf(ma0, w0.x, fmaf(ma1, w0.y, p0));
        p1 = fmaf(ma0, w1.x, fmaf(ma1, w1.y, p1));
        p2 = fmaf(ma0, w2.x, fmaf(ma1, w2.y, p2));
        p3 = fmaf(ma0, w3.x, fmaf(ma1, w3.y, p3));
        q0 = fmaf(mb0, w0.x, fmaf(mb1, w0.y, q0));
        q1 = fmaf(mb0, w1.x, fmaf(mb1, w1.y, q1));
        q2 = fmaf(mb0, w2.x, fmaf(mb1, w2.y, q2));
        q3 = fmaf(mb0, w3.x, fmaf(mb1, w3.y, q3));
    }

    // warp reduce all 8 accumulators
    #pragma unroll
    for (int off = 16; off > 0; off >>= 1) {
        p0 += __shfl_xor_sync(0xFFFFFFFFu, p0, off);
        p1 += __shfl_xor_sync(0xFFFFFFFFu, p1, off);
        p2 += __shfl_xor_sync(0xFFFFFFFFu, p2, off);
        p3 += __shfl_xor_sync(0xFFFFFFFFu, p3, off);
        q0 += __shfl_xor_sync(0xFFFFFFFFu, q0, off);
        q1 += __shfl_xor_sync(0xFFFFFFFFu, q1, off);
        q2 += __shfl_xor_sync(0xFFFFFFFFu, q2, off);
        q3 += __shfl_xor_sync(0xFFFFFFFFu, q3, off);
    }
    const int wid = t >> 5;
    if ((t & 31) == 0) {
        s_red[wid][0] = p0;  s_red[wid][1] = p1;
        s_red[wid][2] = p2;  s_red[wid][3] = p3;
        s_red[wid][4] = q0;  s_red[wid][5] = q1;
        s_red[wid][6] = q2;  s_red[wid][7] = q3;
    }
    __syncthreads();

    // threads 0 and 1 each finish one row
    if (t < 2) {
        const int base = t * 4;
        float l0 = bias4.x, l1 = bias4.y, l2 = bias4.z, l3 = bias4.w;
        #pragma unroll
        for (int w = 0; w < 8; w++) {
            l0 += s_red[w][base + 0];
            l1 += s_red[w][base + 1];
            l2 += s_red[w][base + 2];
            l3 += s_red[w][base + 3];
        }
        const float mx = fmaxf(fmaxf(l0, l1), fmaxf(l2, l3));
        const float e0 = __expf(l0 - mx);
        const float e1 = __expf(l1 - mx);
        const float e2 = __expf(l2 - mx);
        const float e3 = __expf(l3 - mx);
        const float inv = 1.0f / (e0 + e1 + e2 + e3);
        float4 r = make_float4(e0 * inv, e1 * inv, e2 * inv, e3 * inv);
        *reinterpret_cast<float4*>(out + (size_t)(b0 + t) * 4) = r;
    }
}

extern "C" void kernel_launch(void* const* d_in, const int* in_sizes, int n_in,
                              void* d_out, int out_size) {
    const float* x = (const float*)d_in[0];   // [8192,4,16,16,16]
    const float* W = (const float*)d_in[1];   // [4,2048]
    const float* b = (const float*)d_in[2];   // [4]
    float* out = (float*)d_out;               // [8192,4]

    fused_pool_linear_softmax_kernel<<<4097, 256>>>(x, W, b, out);
}

// round 13
// speedup vs baseline: 1.2690x; 1.0020x over previous
#include <cuda_runtime.h>
#include <cuda_bf16.h>
#include <float.h>

// Packed {scale (lo 32b), 1/scale (hi 32b)}. Zero means "not yet published".
// scale > 0 always, so the published value is never 0 — the value is its own
// ready flag. 64-bit accesses are single atomic LDG.64/STG.64.
__device__ volatile unsigned long long g_scale_packed;

// ---------------------------------------------------------------------------
// Single fused kernel, grid 4097 (R12 structure — best measured: 80.1us,
// 84.3% DRAM):
//   block 0     : compute scale = max|W|/7, publish packed {s, 1/s}.
//   blocks 1..N : MaxPool3d(2) + inline int4-dequant linear(2048->4) + bias
//                 + softmax, 2 batch rows per block, CTA-cooperative
//                 contiguous sweeps. Software-pipelined: k+1 x loads are
//                 issued FIRST (DRAM-critical), then k+1 weight loads
//                 (L1-hit), then current-k math. k=0 loads issue before the
//                 scale spin.
//
// Index simplification (t < 256 so (t + k*256)>>8 == k, (t + k*256)&255 == t):
//   off(k) = loff + k*4096,  loff = (t>>5)*512 + ((t>>2)&7)*32 + (t&3)*4
//   f2(k)  = 2t + 512k
//
// x layout: [B, C=4, D=16, H=16, W=16] f32, 16384 floats per row.
// 4 loads per feature-pair: off, off+16, off+256, off+272 (float4,
// sector-complete).
// ---------------------------------------------------------------------------
__global__ void __launch_bounds__(256)
fused_pool_linear_softmax_kernel(const float* __restrict__ x,
                                 const float* __restrict__ W,
                                 const float* __restrict__ bias,
                                 float* __restrict__ out) {
    const int t = threadIdx.x;

    // ---------------- block 0: scale producer ----------------
    if (blockIdx.x == 0) {
        __shared__ float s_warp[8];
        const float4* __restrict__ W4 = reinterpret_cast<const float4*>(W);
        float m = 0.0f;
        #pragma unroll
        for (int k = 0; k < 8; k++) {
            const float4 w = W4[t + k * 256];
            m = fmaxf(m, fmaxf(fmaxf(fabsf(w.x), fabsf(w.y)),
                               fmaxf(fabsf(w.z), fabsf(w.w))));
        }
        #pragma unroll
        for (int off = 16; off > 0; off >>= 1)
            m = fmaxf(m, __shfl_xor_sync(0xFFFFFFFFu, m, off));
        if ((t & 31) == 0) s_warp[t >> 5] = m;
        __syncthreads();
        if (t == 0) {
            float mm = fmaxf(fmaxf(fmaxf(s_warp[0], s_warp[1]),
                                   fmaxf(s_warp[2], s_warp[3])),
                             fmaxf(fmaxf(s_warp[4], s_warp[5]),
                                   fmaxf(s_warp[6], s_warp[7])));
            const float scale = mm / 7.0f;
            const float inv_scale = 1.0f / scale;
            const unsigned long long packed =
                ((unsigned long long)__float_as_uint(inv_scale) << 32) |
                (unsigned long long)__float_as_uint(scale);
            g_scale_packed = packed;   // volatile 64-bit store: flag == data
        }
        return;
    }

    // ---------------- blocks 1..4096: main body ----------------
    __shared__ float s_red[8][8];   // [warp][row0 accs 0..3 | row1 accs 4..7]

    const int b0 = (blockIdx.x - 1) * 2;
    const float* __restrict__ xb0 = x + (size_t)b0 * 16384;
    const float* __restrict__ xb1 = xb0 + 16384;

    const float4 bias4 = *reinterpret_cast<const float4*>(bias);

    float p0 = 0.0f, p1 = 0.0f, p2 = 0.0f, p3 = 0.0f;   // row 0 partials
    float q0 = 0.0f, q1 = 0.0f, q2 = 0.0f, q3 = 0.0f;   // row 1 partials

    const int loff = (t >> 5) * 512 + ((t >> 2) & 7) * 32 + (t & 3) * 4;

    // ===== peeled k=0: issue x loads + raw weight loads BEFORE the spin =====
    const float4* pa0 = reinterpret_cast<const float4*>(xb0 + loff);
    const float4* pb0 = reinterpret_cast<const float4*>(xb1 + loff);
    float4 A0 = __ldcs(pa0);
    float4 A1 = __ldcs(pa0 + 4);
    float4 A2 = __ldcs(pa0 + 64);
    float4 A3 = __ldcs(pa0 + 68);
    float4 C0 = __ldcs(pb0);
    float4 C1 = __ldcs(pb0 + 4);
    float4 C2 = __ldcs(pb0 + 64);
    float4 C3 = __ldcs(pb0 + 68);

    // raw weights for k=0 (scale-independent)
    const int wb = t * 2;
    float2 rw0 = *reinterpret_cast<const float2*>(&W[wb]);
    float2 rw1 = *reinterpret_cast<const float2*>(&W[2048 + wb]);
    float2 rw2 = *reinterpret_cast<const float2*>(&W[4096 + wb]);
    float2 rw3 = *reinterpret_cast<const float2*>(&W[6144 + wb]);

    // Spin for the packed scale; everything above is in flight meanwhile.
    unsigned long long v = g_scale_packed;
    while (v == 0ull) v = g_scale_packed;
    const float scale     = __uint_as_float((unsigned int)v);
    const float inv_scale = __uint_as_float((unsigned int)(v >> 32));

    #pragma unroll
    for (int k = 0; k < 4; k++) {
        // current iteration's weights arrive via rw* (prefetched)
        float2 w0 = rw0, w1 = rw1, w2 = rw2, w3 = rw3;

        // pooled maxes for current k (consumes A*/C*, freeing them)
        const float ma0 = fmaxf(fmaxf(fmaxf(A0.x, A0.y), fmaxf(A1.x, A1.y)),
                                fmaxf(fmaxf(A2.x, A2.y), fmaxf(A3.x, A3.y)));
        const float ma1 = fmaxf(fmaxf(fmaxf(A0.z, A0.w), fmaxf(A1.z, A1.w)),
                                fmaxf(fmaxf(A2.z, A2.w), fmaxf(A3.z, A3.w)));
        const float mb0 = fmaxf(fmaxf(fmaxf(C0.x, C0.y), fmaxf(C1.x, C1.y)),
                                fmaxf(fmaxf(C2.x, C2.y), fmaxf(C3.x, C3.y)));
        const float mb1 = fmaxf(fmaxf(fmaxf(C0.z, C0.w), fmaxf(C1.z, C1.w)),
                                fmaxf(fmaxf(C2.z, C2.w), fmaxf(C3.z, C3.w)));

        // k+1 x loads FIRST (DRAM-critical; off(k+1) = loff + (k+1)*4096)
        if (k < 3) {
            const int off = loff + (k + 1) * 4096;
            const float4* pa = reinterpret_cast<const float4*>(xb0 + off);
            const float4* pb = reinterpret_cast<const float4*>(xb1 + off);
            A0 = __ldcs(pa);
            A1 = __ldcs(pa + 4);
            A2 = __ldcs(pa + 64);
            A3 = __ldcs(pa + 68);
            C0 = __ldcs(pb);
            C1 = __ldcs(pb + 4);
            C2 = __ldcs(pb + 64);
            C3 = __ldcs(pb + 68);
        }

        // k+1 weight prefetch AFTER (L1-hit; f2(k+1) = wb + (k+1)*512)
        if (k < 3) {
            const int nf2 = wb + (k + 1) * 512;
            rw0 = *reinterpret_cast<const float2*>(&W[nf2]);
            rw1 = *reinterpret_cast<const float2*>(&W[2048 + nf2]);
            rw2 = *reinterpret_cast<const float2*>(&W[4096 + nf2]);
            rw3 = *reinterpret_cast<const float2*>(&W[6144 + nf2]);
        }

        // inline int4 dequant (half-to-even; clip(-8,7) never binds)
        w0.x = rintf(w0.x * inv_scale) * scale;
        w0.y = rintf(w0.y * inv_scale) * scale;
        w1.x = rintf(w1.x * inv_scale) * scale;
        w1.y = rintf(w1.y * inv_scale) * scale;
        w2.x = rintf(w2.x * inv_scale) * scale;
        w2.y = rintf(w2.y * inv_scale) * scale;
        w3.x = rintf(w3.x * inv_scale) * scale;
        w3.y = rintf(w3.y * inv_scale) * scale;

        p0 = fmaf(ma0, w0.x, fmaf(ma1, w0.y, p0));
        p1 = fmaf(ma0, w1.x, fmaf(ma1, w1.y, p1));
        p2 = fmaf(ma0, w2.x, fmaf(ma1, w2.y, p2));
        p3 = fmaf(ma0, w3.x, fmaf(ma1, w3.y, p3));
        q0 = fmaf(mb0, w0.x, fmaf(mb1, w0.y, q0));
        q1 = fmaf(mb0, w1.x, fmaf(mb1, w1.y, q1));
        q2 = fmaf(mb0, w2.x, fmaf(mb1, w2.y, q2));
        q3 = fmaf(mb0, w3.x, fmaf(mb1, w3.y, q3));
    }

    // warp reduce all 8 accumulators
    #pragma unroll
    for (int off = 16; off > 0; off >>= 1) {
        p0 += __shfl_xor_sync(0xFFFFFFFFu, p0, off);
        p1 += __shfl_xor_sync(0xFFFFFFFFu, p1, off);
        p2 += __shfl_xor_sync(0xFFFFFFFFu, p2, off);
        p3 += __shfl_xor_sync(0xFFFFFFFFu, p3, off);
        q0 += __shfl_xor_sync(0xFFFFFFFFu, q0, off);
        q1 += __shfl_xor_sync(0xFFFFFFFFu, q1, off);
        q2 += __shfl_xor_sync(0xFFFFFFFFu, q2, off);
        q3 += __shfl_xor_sync(0xFFFFFFFFu, q3, off);
    }
    const int wid = t >> 5;
    if ((t & 31) == 0) {
        s_red[wid][0] = p0;  s_red[wid][1] = p1;
        s_red[wid][2] = p2;  s_red[wid][3] = p3;
        s_red[wid][4] = q0;  s_red[wid][5] = q1;
        s_red[wid][6] = q2;  s_red[wid][7] = q3;
    }
    __syncthreads();

    // threads 0 and 1 each finish one row
    if (t < 2) {
        const int base = t * 4;
        float l0 = bias4.x, l1 = bias4.y, l2 = bias4.z, l3 = bias4.w;
        #pragma unroll
        for (int w = 0; w < 8; w++) {
            l0 += s_red[w][base + 0];
            l1 += s_red[w][base + 1];
            l2 += s_red[w][base + 2];
            l3 += s_red[w][base + 3];
        }
        const float mx = fmaxf(fmaxf(l0, l1), fmaxf(l2, l3));
        const float e0 = __expf(l0 - mx);
        const float e1 = __expf(l1 - mx);
        const float e2 = __expf(l2 - mx);
        const float e3 = __expf(l3 - mx);
        const float inv = 1.0f / (e0 + e1 + e2 + e3);
        float4 r = make_float4(e0 * inv, e1 * inv, e2 * inv, e3 * inv);
        *reinterpret_cast<float4*>(out + (size_t)(b0 + t) * 4) = r;
    }
}

extern "C" void kernel_launch(void* const* d_in, const int* in_sizes, int n_in,
                              void* d_out, int out_size) {
    const float* x = (const float*)d_in[0];   // [8192,4,16,16,16]
    const float* W = (const float*)d_in[1];   // [4,2048]
    const float* b = (const float*)d_in[2];   // [4]
    float* out = (float*)d_out;               // [8192,4]

    fused_pool_linear_softmax_kernel<<<4097, 256>>>(x, W, b, out);
}

// round 14
// speedup vs baseline: 1.2695x; 1.0004x over previous
#include <cuda_runtime.h>
#include <cuda_bf16.h>
#include <float.h>

// Packed {scale (lo 32b), 1/scale (hi 32b)}. Zero means "not yet published".
// scale > 0 always, so the published value is never 0 — the value is its own
// ready flag. 64-bit accesses are single atomic LDG.64/STG.64.
__device__ volatile unsigned long long g_scale_packed;

// ---------------------------------------------------------------------------
// Single fused kernel, grid 4097 (R13 structure — best measured: 79.9us,
// 85.4% DRAM — with ALL weight loads hoisted out of the streaming loop):
//   block 0     : compute scale = max|W|/7, publish packed {s, 1/s}.
//   blocks 1..N : MaxPool3d(2) + int4-dequant linear(2048->4) + bias
//                 + softmax, 2 batch rows per block, CTA-cooperative
//                 contiguous sweeps.
// All 16 weight float2 (128B/thread, covering every k-iter) are loaded BEFORE
// the scale spin and dequantized once right after it. The main loop then
// issues ONLY the 16 DRAM-critical LDG.128 per iteration + math: no L1
// round-trips, no weight scoreboard waits, no per-iter weight address ALU.
//
// Index simplification (t < 256): off(k) = loff + k*4096,
//   loff = (t>>5)*512 + ((t>>2)&7)*32 + (t&3)*4 ; weights at 2t + 512k.
// x layout: [B, C=4, D=16, H=16, W=16] f32, 16384 floats per row.
// 4 loads per feature-pair: off, off+16, off+256, off+272 (float4,
// sector-complete).
// ---------------------------------------------------------------------------
__global__ void __launch_bounds__(256)
fused_pool_linear_softmax_kernel(const float* __restrict__ x,
                                 const float* __restrict__ W,
                                 const float* __restrict__ bias,
                                 float* __restrict__ out) {
    const int t = threadIdx.x;

    // ---------------- block 0: scale producer ----------------
    if (blockIdx.x == 0) {
        __shared__ float s_warp[8];
        const float4* __restrict__ W4 = reinterpret_cast<const float4*>(W);
        float m = 0.0f;
        #pragma unroll
        for (int k = 0; k < 8; k++) {
            const float4 w = W4[t + k * 256];
            m = fmaxf(m, fmaxf(fmaxf(fabsf(w.x), fabsf(w.y)),
                               fmaxf(fabsf(w.z), fabsf(w.w))));
        }
        #pragma unroll
        for (int off = 16; off > 0; off >>= 1)
            m = fmaxf(m, __shfl_xor_sync(0xFFFFFFFFu, m, off));
        if ((t & 31) == 0) s_warp[t >> 5] = m;
        __syncthreads();
        if (t == 0) {
            float mm = fmaxf(fmaxf(fmaxf(s_warp[0], s_warp[1]),
                                   fmaxf(s_warp[2], s_warp[3])),
                             fmaxf(fmaxf(s_warp[4], s_warp[5]),
                                   fmaxf(s_warp[6], s_warp[7])));
            const float scale = mm / 7.0f;
            const float inv_scale = 1.0f / scale;
            const unsigned long long packed =
                ((unsigned long long)__float_as_uint(inv_scale) << 32) |
                (unsigned long long)__float_as_uint(scale);
            g_scale_packed = packed;   // volatile 64-bit store: flag == data
        }
        return;
    }

    // ---------------- blocks 1..4096: main body ----------------
    __shared__ float s_red[8][8];   // [warp][row0 accs 0..3 | row1 accs 4..7]

    const int b0 = (blockIdx.x - 1) * 2;
    const float* __restrict__ xb0 = x + (size_t)b0 * 16384;
    const float* __restrict__ xb1 = xb0 + 16384;

    const float4 bias4 = *reinterpret_cast<const float4*>(bias);

    float p0 = 0.0f, p1 = 0.0f, p2 = 0.0f, p3 = 0.0f;   // row 0 partials
    float q0 = 0.0f, q1 = 0.0f, q2 = 0.0f, q3 = 0.0f;   // row 1 partials

    const int loff = (t >> 5) * 512 + ((t >> 2) & 7) * 32 + (t & 3) * 4;
    const int wb   = t * 2;

    // ===== pre-spin: issue k=0 x loads AND all 16 weight loads =====
    const float4* pa0 = reinterpret_cast<const float4*>(xb0 + loff);
    const float4* pb0 = reinterpret_cast<const float4*>(xb1 + loff);
    float4 A0 = __ldcs(pa0);
    float4 A1 = __ldcs(pa0 + 4);
    float4 A2 = __ldcs(pa0 + 64);
    float4 A3 = __ldcs(pa0 + 68);
    float4 C0 = __ldcs(pb0);
    float4 C1 = __ldcs(pb0 + 4);
    float4 C2 = __ldcs(pb0 + 64);
    float4 C3 = __ldcs(pb0 + 68);

    // all weights for k=0..3, outputs 0..3 (scale-independent raw loads)
    float2 wv[4][4];   // wv[k][o]
    #pragma unroll
    for (int k = 0; k < 4; k++) {
        const int f2 = wb + k * 512;
        wv[k][0] = *reinterpret_cast<const float2*>(&W[f2]);
        wv[k][1] = *reinterpret_cast<const float2*>(&W[2048 + f2]);
        wv[k][2] = *reinterpret_cast<const float2*>(&W[4096 + f2]);
        wv[k][3] = *reinterpret_cast<const float2*>(&W[6144 + f2]);
    }

    // Spin for the packed scale; all loads above are in flight meanwhile.
    unsigned long long v = g_scale_packed;
    while (v == 0ull) v = g_scale_packed;
    const float scale     = __uint_as_float((unsigned int)v);
    const float inv_scale = __uint_as_float((unsigned int)(v >> 32));

    // dequantize all weights once (half-to-even; clip(-8,7) never binds)
    #pragma unroll
    for (int k = 0; k < 4; k++) {
        #pragma unroll
        for (int o = 0; o < 4; o++) {
            wv[k][o].x = rintf(wv[k][o].x * inv_scale) * scale;
            wv[k][o].y = rintf(wv[k][o].y * inv_scale) * scale;
        }
    }

    // ===== streaming loop: ONLY x loads + math =====
    #pragma unroll
    for (int k = 0; k < 4; k++) {
        // pooled maxes for current k (consumes A*/C*, freeing them)
        const float ma0 = fmaxf(fmaxf(fmaxf(A0.x, A0.y), fmaxf(A1.x, A1.y)),
                                fmaxf(fmaxf(A2.x, A2.y), fmaxf(A3.x, A3.y)));
        const float ma1 = fmaxf(fmaxf(fmaxf(A0.z, A0.w), fmaxf(A1.z, A1.w)),
                                fmaxf(fmaxf(A2.z, A2.w), fmaxf(A3.z, A3.w)));
        const float mb0 = fmaxf(fmaxf(fmaxf(C0.x, C0.y), fmaxf(C1.x, C1.y)),
                                fmaxf(fmaxf(C2.x, C2.y), fmaxf(C3.x, C3.y)));
        const float mb1 = fmaxf(fmaxf(fmaxf(C0.z, C0.w), fmaxf(C1.z, C1.w)),
                                fmaxf(fmaxf(C2.z, C2.w), fmaxf(C3.z, C3.w)));

        // k+1 x loads immediately (DRAM-critical)
        if (k < 3) {
            const int off = loff + (k + 1) * 4096;
            const float4* pa = reinterpret_cast<const float4*>(xb0 + off);
            const float4* pb = reinterpret_cast<const float4*>(xb1 + off);
            A0 = __ldcs(pa);
            A1 = __ldcs(pa + 4);
            A2 = __ldcs(pa + 64);
            A3 = __ldcs(pa + 68);
            C0 = __ldcs(pb);
            C1 = __ldcs(pb + 4);
            C2 = __ldcs(pb + 64);
            C3 = __ldcs(pb + 68);
        }

        p0 = fmaf(ma0, wv[k][0].x, fmaf(ma1, wv[k][0].y, p0));
        p1 = fmaf(ma0, wv[k][1].x, fmaf(ma1, wv[k][1].y, p1));
        p2 = fmaf(ma0, wv[k][2].x, fmaf(ma1, wv[k][2].y, p2));
        p3 = fmaf(ma0, wv[k][3].x, fmaf(ma1, wv[k][3].y, p3));
        q0 = fmaf(mb0, wv[k][0].x, fmaf(mb1, wv[k][0].y, q0));
        q1 = fmaf(mb0, wv[k][1].x, fmaf(mb1, wv[k][1].y, q1));
        q2 = fmaf(mb0, wv[k][2].x, fmaf(mb1, wv[k][2].y, q2));
        q3 = fmaf(mb0, wv[k][3].x, fmaf(mb1, wv[k][3].y, q3));
    }

    // warp reduce all 8 accumulators
    #pragma unroll
    for (int off = 16; off > 0; off >>= 1) {
        p0 += __shfl_xor_sync(0xFFFFFFFFu, p0, off);
        p1 += __shfl_xor_sync(0xFFFFFFFFu, p1, off);
        p2 += __shfl_xor_sync(0xFFFFFFFFu, p2, off);
        p3 += __shfl_xor_sync(0xFFFFFFFFu, p3, off);
        q0 += __shfl_xor_sync(0xFFFFFFFFu, q0, off);
        q1 += __shfl_xor_sync(0xFFFFFFFFu, q1, off);
        q2 += __shfl_xor_sync(0xFFFFFFFFu, q2, off);
        q3 += __shfl_xor_sync(0xFFFFFFFFu, q3, off);
    }
    const int wid = t >> 5;
    if ((t & 31) == 0) {
        s_red[wid][0] = p0;  s_red[wid][1] = p1;
        s_red[wid][2] = p2;  s_red[wid][3] = p3;
        s_red[wid][4] = q0;  s_red[wid][5] = q1;
        s_red[wid][6] = q2;  s_red[wid][7] = q3;
    }
    __syncthreads();

    // threads 0 and 1 each finish one row
    if (t < 2) {
        const int base = t * 4;
        float l0 = bias4.x, l1 = bias4.y, l2 = bias4.z, l3 = bias4.w;
        #pragma unroll
        for (int w = 0; w < 8; w++) {
            l0 += s_red[w][base + 0];
            l1 += s_red[w][base + 1];
            l2 += s_red[w][base + 2];
            l3 += s_red[w][base + 3];
        }
        const float mx = fmaxf(fmaxf(l0, l1), fmaxf(l2, l3));
        const float e0 = __expf(l0 - mx);
        const float e1 = __expf(l1 - mx);
        const float e2 = __expf(l2 - mx);
        const float e3 = __expf(l3 - mx);
        const float inv = 1.0f / (e0 + e1 + e2 + e3);
        float4 r = make_float4(e0 * inv, e1 * inv, e2 * inv, e3 * inv);
        *reinterpret_cast<float4*>(out + (size_t)(b0 + t) * 4) = r;
    }
}

extern "C" void kernel_launch(void* const* d_in, const int* in_sizes, int n_in,
                              void* d_out, int out_size) {
    const float* x = (const float*)d_in[0];   // [8192,4,16,16,16]
    const float* W = (const float*)d_in[1];   // [4,2048]
    const float* b = (const float*)d_in[2];   // [4]
    float* out = (float*)d_out;               // [8192,4]

    fused_pool_linear_softmax_kernel<<<4097, 256>>>(x, W, b, out);
}

// round 15
// speedup vs baseline: 1.3024x; 1.0259x over previous
#include <cuda_runtime.h>
#include <cuda_bf16.h>
#include <float.h>

// Packed {scale (lo 32b), 1/scale (hi 32b)}. Zero means "not yet published".
// scale > 0 always, so the published value is never 0 — the value is its own
// ready flag. 64-bit accesses are single atomic LDG.64/STG.64.
__device__ volatile unsigned long long g_scale_packed;

// ---------------------------------------------------------------------------
// Single fused kernel, grid 4097 (R14 structure — best: 79.9us, 85.9% DRAM —
// with the x-load pipeline deepened to prefetch distance 2):
//   block 0     : compute scale = max|W|/7, publish packed {s, 1/s}.
//   blocks 1..N : MaxPool3d(2) + int4-dequant linear(2048->4) + bias
//                 + softmax, 2 batch rows per block, CTA-cooperative
//                 contiguous sweeps.
// All 16 weight float2 are preloaded before the scale spin and dequantized
// once. x loads run a 2-deep pipeline: while processing iter k, loads for
// k+1 AND k+2 are in flight (16 LDG.128 outstanding per thread).
//
// Index: off(k) = loff + k*4096, loff = (t>>5)*512 + ((t>>2)&7)*32 + (t&3)*4.
// x layout: [B, C=4, D=16, H=16, W=16] f32, 16384 floats per row.
// 4 loads per feature-pair: off, off+16, off+256, off+272 (float4,
// sector-complete).
// ---------------------------------------------------------------------------
__global__ void __launch_bounds__(256)
fused_pool_linear_softmax_kernel(const float* __restrict__ x,
                                 const float* __restrict__ W,
                                 const float* __restrict__ bias,
                                 float* __restrict__ out) {
    const int t = threadIdx.x;

    // ---------------- block 0: scale producer ----------------
    if (blockIdx.x == 0) {
        __shared__ float s_warp[8];
        const float4* __restrict__ W4 = reinterpret_cast<const float4*>(W);
        float m = 0.0f;
        #pragma unroll
        for (int k = 0; k < 8; k++) {
            const float4 w = W4[t + k * 256];
            m = fmaxf(m, fmaxf(fmaxf(fabsf(w.x), fabsf(w.y)),
                               fmaxf(fabsf(w.z), fabsf(w.w))));
        }
        #pragma unroll
        for (int off = 16; off > 0; off >>= 1)
            m = fmaxf(m, __shfl_xor_sync(0xFFFFFFFFu, m, off));
        if ((t & 31) == 0) s_warp[t >> 5] = m;
        __syncthreads();
        if (t == 0) {
            float mm = fmaxf(fmaxf(fmaxf(s_warp[0], s_warp[1]),
                                   fmaxf(s_warp[2], s_warp[3])),
                             fmaxf(fmaxf(s_warp[4], s_warp[5]),
                                   fmaxf(s_warp[6], s_warp[7])));
            const float scale = mm / 7.0f;
            const float inv_scale = 1.0f / scale;
            const unsigned long long packed =
                ((unsigned long long)__float_as_uint(inv_scale) << 32) |
                (unsigned long long)__float_as_uint(scale);
            g_scale_packed = packed;   // volatile 64-bit store: flag == data
        }
        return;
    }

    // ---------------- blocks 1..4096: main body ----------------
    __shared__ float s_red[8][8];   // [warp][row0 accs 0..3 | row1 accs 4..7]

    const int b0 = (blockIdx.x - 1) * 2;
    const float* __restrict__ xb0 = x + (size_t)b0 * 16384;
    const float* __restrict__ xb1 = xb0 + 16384;

    const float4 bias4 = *reinterpret_cast<const float4*>(bias);

    float p0 = 0.0f, p1 = 0.0f, p2 = 0.0f, p3 = 0.0f;   // row 0 partials
    float q0 = 0.0f, q1 = 0.0f, q2 = 0.0f, q3 = 0.0f;   // row 1 partials

    const int loff = (t >> 5) * 512 + ((t >> 2) & 7) * 32 + (t & 3) * 4;
    const int wb   = t * 2;

    // ===== pre-spin: issue k=0 AND k=1 x loads, plus all weight loads =====
    const float4* pa0 = reinterpret_cast<const float4*>(xb0 + loff);
    const float4* pb0 = reinterpret_cast<const float4*>(xb1 + loff);
    float4 A0 = __ldcs(pa0);
    float4 A1 = __ldcs(pa0 + 4);
    float4 A2 = __ldcs(pa0 + 64);
    float4 A3 = __ldcs(pa0 + 68);
    float4 C0 = __ldcs(pb0);
    float4 C1 = __ldcs(pb0 + 4);
    float4 C2 = __ldcs(pb0 + 64);
    float4 C3 = __ldcs(pb0 + 68);

    const float4* pa1 = reinterpret_cast<const float4*>(xb0 + loff + 4096);
    const float4* pb1 = reinterpret_cast<const float4*>(xb1 + loff + 4096);
    float4 B0 = __ldcs(pa1);
    float4 B1 = __ldcs(pa1 + 4);
    float4 B2 = __ldcs(pa1 + 64);
    float4 B3 = __ldcs(pa1 + 68);
    float4 D0 = __ldcs(pb1);
    float4 D1 = __ldcs(pb1 + 4);
    float4 D2 = __ldcs(pb1 + 64);
    float4 D3 = __ldcs(pb1 + 68);

    // all weights for k=0..3, outputs 0..3 (scale-independent raw loads)
    float2 wv[4][4];   // wv[k][o]
    #pragma unroll
    for (int k = 0; k < 4; k++) {
        const int f2 = wb + k * 512;
        wv[k][0] = *reinterpret_cast<const float2*>(&W[f2]);
        wv[k][1] = *reinterpret_cast<const float2*>(&W[2048 + f2]);
        wv[k][2] = *reinterpret_cast<const float2*>(&W[4096 + f2]);
        wv[k][3] = *reinterpret_cast<const float2*>(&W[6144 + f2]);
    }

    // Spin for the packed scale; all loads above are in flight meanwhile.
    unsigned long long v = g_scale_packed;
    while (v == 0ull) v = g_scale_packed;
    const float scale     = __uint_as_float((unsigned int)v);
    const float inv_scale = __uint_as_float((unsigned int)(v >> 32));

    // dequantize all weights once (half-to-even; clip(-8,7) never binds)
    #pragma unroll
    for (int k = 0; k < 4; k++) {
        #pragma unroll
        for (int o = 0; o < 4; o++) {
            wv[k][o].x = rintf(wv[k][o].x * inv_scale) * scale;
            wv[k][o].y = rintf(wv[k][o].y * inv_scale) * scale;
        }
    }

    // ===== streaming loop, 2-deep pipeline =====
    // slot A/C holds even k, slot B/D holds odd k.
    #pragma unroll
    for (int k = 0; k < 4; k++) {
        float ma0, ma1, mb0, mb1;
        if ((k & 1) == 0) {
            ma0 = fmaxf(fmaxf(fmaxf(A0.x, A0.y), fmaxf(A1.x, A1.y)),
                        fmaxf(fmaxf(A2.x, A2.y), fmaxf(A3.x, A3.y)));
            ma1 = fmaxf(fmaxf(fmaxf(A0.z, A0.w), fmaxf(A1.z, A1.w)),
                        fmaxf(fmaxf(A2.z, A2.w), fmaxf(A3.z, A3.w)));
            mb0 = fmaxf(fmaxf(fmaxf(C0.x, C0.y), fmaxf(C1.x, C1.y)),
                        fmaxf(fmaxf(C2.x, C2.y), fmaxf(C3.x, C3.y)));
            mb1 = fmaxf(fmaxf(fmaxf(C0.z, C0.w), fmaxf(C1.z, C1.w)),
                        fmaxf(fmaxf(C2.z, C2.w), fmaxf(C3.z, C3.w)));
            // refill even slot with k+2
            if (k + 2 < 4) {
                const int off = loff + (k + 2) * 4096;
                const float4* pa = reinterpret_cast<const float4*>(xb0 + off);
                const float4* pb = reinterpret_cast<const float4*>(xb1 + off);
                A0 = __ldcs(pa);
                A1 = __ldcs(pa + 4);
                A2 = __ldcs(pa + 64);
                A3 = __ldcs(pa + 68);
                C0 = __ldcs(pb);
                C1 = __ldcs(pb + 4);
                C2 = __ldcs(pb + 64);
                C3 = __ldcs(pb + 68);
            }
        } else {
            ma0 = fmaxf(fmaxf(fmaxf(B0.x, B0.y), fmaxf(B1.x, B1.y)),
                        fmaxf(fmaxf(B2.x, B2.y), fmaxf(B3.x, B3.y)));
            ma1 = fmaxf(fmaxf(fmaxf(B0.z, B0.w), fmaxf(B1.z, B1.w)),
                        fmaxf(fmaxf(B2.z, B2.w), fmaxf(B3.z, B3.w)));
            mb0 = fmaxf(fmaxf(fmaxf(D0.x, D0.y), fmaxf(D1.x, D1.y)),
                        fmaxf(fmaxf(D2.x, D2.y), fmaxf(D3.x, D3.y)));
            mb1 = fmaxf(fmaxf(fmaxf(D0.z, D0.w), fmaxf(D1.z, D1.w)),
                        fmaxf(fmaxf(D2.z, D2.w), fmaxf(D3.z, D3.w)));
            // refill odd slot with k+2
            if (k + 2 < 4) {
                const int off = loff + (k + 2) * 4096;
                const float4* pa = reinterpret_cast<const float4*>(xb0 + off);
                const float4* pb = reinterpret_cast<const float4*>(xb1 + off);
                B0 = __ldcs(pa);
                B1 = __ldcs(pa + 4);
                B2 = __ldcs(pa + 64);
                B3 = __ldcs(pa + 68);
                D0 = __ldcs(pb);
                D1 = __ldcs(pb + 4);
                D2 = __ldcs(pb + 64);
                D3 = __ldcs(pb + 68);
            }
        }

        p0 = fmaf(ma0, wv[k][0].x, fmaf(ma1, wv[k][0].y, p0));
        p1 = fmaf(ma0, wv[k][1].x, fmaf(ma1, wv[k][1].y, p1));
        p2 = fmaf(ma0, wv[k][2].x, fmaf(ma1, wv[k][2].y, p2));
        p3 = fmaf(ma0, wv[k][3].x, fmaf(ma1, wv[k][3].y, p3));
        q0 = fmaf(mb0, wv[k][0].x, fmaf(mb1, wv[k][0].y, q0));
        q1 = fmaf(mb0, wv[k][1].x, fmaf(mb1, wv[k][1].y, q1));
        q2 = fmaf(mb0, wv[k][2].x, fmaf(mb1, wv[k][2].y, q2));
        q3 = fmaf(mb0, wv[k][3].x, fmaf(mb1, wv[k][3].y, q3));
    }

    // warp reduce all 8 accumulators
    #pragma unroll
    for (int off = 16; off > 0; off >>= 1) {
        p0 += __shfl_xor_sync(0xFFFFFFFFu, p0, off);
        p1 += __shfl_xor_sync(0xFFFFFFFFu, p1, off);
        p2 += __shfl_xor_sync(0xFFFFFFFFu, p2, off);
        p3 += __shfl_xor_sync(0xFFFFFFFFu, p3, off);
        q0 += __shfl_xor_sync(0xFFFFFFFFu, q0, off);
        q1 += __shfl_xor_sync(0xFFFFFFFFu, q1, off);
        q2 += __shfl_xor_sync(0xFFFFFFFFu, q2, off);
        q3 += __shfl_xor_sync(0xFFFFFFFFu, q3, off);
    }
    const int wid = t >> 5;
    if ((t & 31) == 0) {
        s_red[wid][0] = p0;  s_red[wid][1] = p1;
        s_red[wid][2] = p2;  s_red[wid][3] = p3;
        s_red[wid][4] = q0;  s_red[wid][5] = q1;
        s_red[wid][6] = q2;  s_red[wid][7] = q3;
    }
    __syncthreads();

    // threads 0 and 1 each finish one row
    if (t < 2) {
        const int base = t * 4;
        float l0 = bias4.x, l1 = bias4.y, l2 = bias4.z, l3 = bias4.w;
        #pragma unroll
        for (int w = 0; w < 8; w++) {
            l0 += s_red[w][base + 0];
            l1 += s_red[w][base + 1];
            l2 += s_red[w][base + 2];
            l3 += s_red[w][base + 3];
        }
        const float mx = fmaxf(fmaxf(l0, l1), fmaxf(l2, l3));
        const float e0 = __expf(l0 - mx);
        const float e1 = __expf(l1 - mx);
        const float e2 = __expf(l2 - mx);
        const float e3 = __expf(l3 - mx);
        const float inv = 1.0f / (e0 + e1 + e2 + e3);
        float4 r = make_float4(e0 * inv, e1 * inv, e2 * inv, e3 * inv);
        *reinterpret_cast<float4*>(out + (size_t)(b0 + t) * 4) = r;
    }
}

extern "C" void kernel_launch(void* const* d_in, const int* in_sizes, int n_in,
                              void* d_out, int out_size) {
    const float* x = (const float*)d_in[0];   // [8192,4,16,16,16]
    const float* W = (const float*)d_in[1];   // [4,2048]
    const float* b = (const float*)d_in[2];   // [4]
    float* out = (float*)d_out;               // [8192,4]

    fused_pool_linear_softmax_kernel<<<4097, 256>>>(x, W, b, out);
}